// round 16
// baseline (speedup 1.0000x reference)
#include <cuda_runtime.h>
#include <cuda_bf16.h>
#include <cstdint>

#define DIMD 128
#define SAMP 12
#define RPT  5             // item rows per tile (divides 3200 and 38400 exactly)
#define MROWS 60           // GEMM rows per tile (padded to 64 in the A planes)
#define NT   256           // 8 warps; warp grid 2(m)x4(n): m32 x n32 per warp

// ---- agg smem byte offsets (dynamic), total 104704 -> 2 CTAs/SM ----
#define BHI_OFF   0          // W1^T bf16 hi [128 n][128 k] swizzled      32768
#define BLO_OFF   32768      // lo                                        32768
#define AHI_OFF   65536      // A bf16 hi [64 m][128 k] swizzled          16384
#define ALO_OFF   81920      // lo                                        16384
#define ITEM_OFF  98304      // item fp32 [5][128]                         2560
#define NW_OFF    100864     // 60 floats                                   256
#define LGP_OFF   101120     // logit partials [8 warps][64]               2048
#define LG_OFF    103168     // 60 logits                                   256
#define AL_OFF    103424     // 60 alphas                                   256
#define BIAS_OFF  103680     // 128 floats (W1 row D)                       512
#define W2_OFF    104192     // 128 floats                                  512
#define SMEM_TOTAL 104704

static __device__ __forceinline__ uint32_t smem_u32(const void* p) {
    uint32_t a;
    asm("{ .reg .u64 t; cvta.to.shared.u64 t, %1; cvt.u32.u64 %0, t; }" : "=r"(a) : "l"(p));
    return a;
}
static __device__ __forceinline__ void ldsm4(uint32_t &r0, uint32_t &r1, uint32_t &r2, uint32_t &r3,
                                             uint32_t addr) {
    asm volatile("ldmatrix.sync.aligned.m8n8.x4.shared.b16 {%0,%1,%2,%3}, [%4];"
                 : "=r"(r0), "=r"(r1), "=r"(r2), "=r"(r3) : "r"(addr));
}
static __device__ __forceinline__ void mma_bf16(float* d, const uint32_t* a, uint32_t b0, uint32_t b1) {
    asm volatile("mma.sync.aligned.m16n8k16.row.col.f32.bf16.bf16.f32 "
                 "{%0,%1,%2,%3}, {%4,%5,%6,%7}, {%8,%9}, {%0,%1,%2,%3};"
                 : "+f"(d[0]), "+f"(d[1]), "+f"(d[2]), "+f"(d[3])
                 : "r"(a[0]), "r"(a[1]), "r"(a[2]), "r"(a[3]), "r"(b0), "r"(b1));
}

// ---- scratch (no allocations allowed: device globals) ----
__device__ float g_a0[64*50*128];
__device__ float g_a1[64*600*128];
__device__ float g_b0[64*50*128];

// Two independent attention-aggregate stages in one persistent launch.
// Tiles [0, tiles0) use set 0; tiles [tiles0, tilesTotal) use set 1.
// M=64 tiles, B (W1) resident in smem, nb streamed from gmem (L2 on re-read).
__global__ void __launch_bounds__(NT, 2)
agg_kernel(const float* __restrict__ item0, const float* __restrict__ nb0a,
           const float* __restrict__ nw0a,  float* __restrict__ out0, int tiles0,
           const float* __restrict__ item1, const float* __restrict__ nb1a,
           const float* __restrict__ nw1a,  float* __restrict__ out1, int tilesTotal,
           const float* __restrict__ w1,    const float* __restrict__ w2)
{
    extern __shared__ __align__(128) char sm[];
    const uint32_t smb = smem_u32(sm);
    const int tid  = threadIdx.x;
    const int lane = tid & 31;
    const int warp = tid >> 5;          // 0..7
    const int wm   = warp >> 2;         // m-half: rows [32wm, 32wm+32)
    const int wn   = warp & 3;          // n-slice: cols [32wn, 32wn+32)

    // ---- startup: stage W1^T hi/lo bf16 (swizzled) into persistent B planes ----
    for (int i = tid; i < DIMD*DIMD; i += NT) {
        int d = i >> 7, n = i & 127;                 // w1[d][n]
        float w = w1[i];
        __nv_bfloat16 hb = __float2bfloat16(w);
        __nv_bfloat16 lb = __float2bfloat16(w - __bfloat162float(hb));
        uint32_t off = (uint32_t)n*256u + ((uint32_t)(((d>>3) ^ (n & 7))) << 4) + ((uint32_t)(d & 7) << 1);
        *(__nv_bfloat16*)(sm + BHI_OFF + off) = hb;
        *(__nv_bfloat16*)(sm + BLO_OFF + off) = lb;
    }
    if (tid < DIMD) {
        ((float*)(sm + BIAS_OFF))[tid] = w1[DIMD*DIMD + tid];
        ((float*)(sm + W2_OFF))[tid]   = w2[tid];
    }
    // zero A-plane rows 60..63 (never written per-tile): 64 float4 per plane
    if (tid < 128) {
        const uint32_t plane = (tid < 64) ? AHI_OFF : ALO_OFF;
        const int idx = tid & 63;
        *(float4*)(sm + plane + 60*256 + idx*16) = make_float4(0.f,0.f,0.f,0.f);
    }
    __syncthreads();

    const float* nwf   = (const float*)(sm + NW_OFF);
    const float* biasf = (const float*)(sm + BIAS_OFF);
    const float* w2f   = (const float*)(sm + W2_OFF);
    float* lgpart = (float*)(sm + LGP_OFF);
    float* lgf    = (float*)(sm + LG_OFF);
    float* alf    = (float*)(sm + AL_OFF);

    // per-lane fragment addressing constants
    const uint32_t aLaneRow = (uint32_t)(lane & 15) * 256u;
    const uint32_t aCk      = (uint32_t)(lane >> 4);
    const uint32_t aSwz     = (uint32_t)(lane & 7);
    const uint32_t l7       = (uint32_t)(lane & 7);
    const uint32_t ck4      = ((uint32_t)lane >> 3) & 3;

    for (int ti = blockIdx.x; ti < tilesTotal; ti += gridDim.x) {
        const int loc = (ti < tiles0) ? ti : (ti - tiles0);
        const int rowBase = loc * RPT;
        const float* itemp = (ti < tiles0) ? item0 : item1;
        const float* nbp   = (ti < tiles0) ? nb0a : nb1a;
        const float* nwp   = (ti < tiles0) ? nw0a : nw1a;
        float* outp        = (ti < tiles0) ? out0 : out1;

        // ---- stage item rows + neighbor weights ----
        if (tid < RPT*32)
            ((float4*)(sm + ITEM_OFF))[tid] = ((const float4*)itemp)[(size_t)rowBase*32 + tid];
        if (tid < MROWS)
            ((float*)(sm + NW_OFF))[tid] = nwp[(size_t)rowBase*SAMP + tid];
        __syncthreads();

        // ---- convert: A = bf16 hi/lo(item ⊙ nb) into swizzled planes (nb from gmem) ----
        {
            const float4* nbsrc = (const float4*)nbp + (size_t)rowBase*(SAMP*32);
            #pragma unroll
            for (int k = 0; k < 8; k++) {            // 1920 granules total
                const int i = tid + k*NT;
                if (k == 7 && i >= MROWS*32) break;
                const int rs = i >> 5, j = i & 31;
                float4 v  = nbsrc[i];
                float4 it = *(const float4*)(sm + ITEM_OFF + (size_t)(rs/SAMP)*512 + (size_t)j*16);
                float m0 = v.x*it.x, m1 = v.y*it.y, m2 = v.z*it.z, m3 = v.w*it.w;
                __nv_bfloat162 h01 = __floats2bfloat162_rn(m0, m1);
                __nv_bfloat162 h23 = __floats2bfloat162_rn(m2, m3);
                float2 f01 = __bfloat1622float2(h01);
                float2 f23 = __bfloat1622float2(h23);
                __nv_bfloat162 l01 = __floats2bfloat162_rn(m0 - f01.x, m1 - f01.y);
                __nv_bfloat162 l23 = __floats2bfloat162_rn(m2 - f23.x, m3 - f23.y);
                uint32_t off = (uint32_t)rs*256u + ((uint32_t)(((j>>1) ^ (rs & 7))) << 4) + ((uint32_t)(j & 1) << 3);
                *(__nv_bfloat162*)(sm + AHI_OFF + off)     = h01;
                *(__nv_bfloat162*)(sm + AHI_OFF + off + 4) = h23;
                *(__nv_bfloat162*)(sm + ALO_OFF + off)     = l01;
                *(__nv_bfloat162*)(sm + ALO_OFF + off + 4) = l23;
            }
        }
        __syncthreads();

        // ---- MMA: warp computes D[32wm:32wm+32, 32wn:32wn+32]; B from smem ----
        float d[2][4][4];
        #pragma unroll
        for (int s = 0; s < 2; s++)
            #pragma unroll
            for (int j = 0; j < 4; j++)
                #pragma unroll
                for (int i = 0; i < 4; i++) d[s][j][i] = 0.f;

        #pragma unroll
        for (int p = 0; p < 4; p++) {
            uint32_t Bh[4][4], Bl[4][4];   // [j][frag]: covers q=2p (0,1) and q=2p+1 (2,3)
            #pragma unroll
            for (int j = 0; j < 4; j++) {
                const uint32_t row8 = (uint32_t)(wn*32 + j*8) + l7;
                const uint32_t term = row8*256u + ((((uint32_t)(4*p) + ck4) ^ (row8 & 7)) << 4);
                ldsm4(Bh[j][0], Bh[j][1], Bh[j][2], Bh[j][3], smb + BHI_OFF + term);
                ldsm4(Bl[j][0], Bl[j][1], Bl[j][2], Bl[j][3], smb + BLO_OFF + term);
            }
            #pragma unroll
            for (int qq = 0; qq < 2; qq++) {
                const int q = 2*p + qq;
                const uint32_t koff = ((((uint32_t)(2*q) + aCk) ^ aSwz) << 4);
                #pragma unroll
                for (int s = 0; s < 2; s++) {
                    const uint32_t aoff = (uint32_t)(wm*2 + s)*4096u + aLaneRow + koff;
                    uint32_t ah[4], al[4];
                    ldsm4(ah[0], ah[1], ah[2], ah[3], smb + AHI_OFF + aoff);
                    ldsm4(al[0], al[1], al[2], al[3], smb + ALO_OFF + aoff);
                    #pragma unroll
                    for (int j = 0; j < 4; j++) mma_bf16(d[s][j], ah, Bh[j][qq*2], Bh[j][qq*2+1]);
                    #pragma unroll
                    for (int j = 0; j < 4; j++) mma_bf16(d[s][j], al, Bh[j][qq*2], Bh[j][qq*2+1]);
                    #pragma unroll
                    for (int j = 0; j < 4; j++) mma_bf16(d[s][j], ah, Bl[j][qq*2], Bl[j][qq*2+1]);
                }
            }
        }

        // ---- logit partials: bias*nw + leaky + dot(w2) over this warp's 32 cols ----
        {
            const int lq = lane & 3;
            const int rq = lane >> 2;
            #pragma unroll
            for (int s = 0; s < 2; s++) {
                const int r0 = wm*32 + s*16 + rq;      // <= 55 < 60
                const int r1 = r0 + 8;                 // <= 63, guard < 60
                const float nw0 = nwf[r0];
                const float nw1 = nwf[r1 < MROWS ? r1 : 0];
                float lg0 = 0.f, lg1 = 0.f;
                #pragma unroll
                for (int j = 0; j < 4; j++) {
                    const int c0 = wn*32 + j*8 + lq*2;
                    const float b0v = biasf[c0], b1v = biasf[c0+1];
                    const float v0  = w2f[c0],   v1  = w2f[c0+1];
                    float y;
                    y = d[s][j][0] + nw0*b0v; y = fmaxf(y,0.f) + 0.2f*fminf(y,0.f); lg0 = fmaf(y, v0, lg0);
                    y = d[s][j][1] + nw0*b1v; y = fmaxf(y,0.f) + 0.2f*fminf(y,0.f); lg0 = fmaf(y, v1, lg0);
                    y = d[s][j][2] + nw1*b0v; y = fmaxf(y,0.f) + 0.2f*fminf(y,0.f); lg1 = fmaf(y, v0, lg1);
                    y = d[s][j][3] + nw1*b1v; y = fmaxf(y,0.f) + 0.2f*fminf(y,0.f); lg1 = fmaf(y, v1, lg1);
                }
                lg0 += __shfl_xor_sync(0xffffffffu, lg0, 1);
                lg0 += __shfl_xor_sync(0xffffffffu, lg0, 2);
                lg1 += __shfl_xor_sync(0xffffffffu, lg1, 1);
                lg1 += __shfl_xor_sync(0xffffffffu, lg1, 2);
                if (lq == 0) {
                    lgpart[warp*64 + r0] = lg0;
                    if (r1 < MROWS) lgpart[warp*64 + r1] = lg1;
                }
            }
        }
        __syncthreads();

        // ---- reduce partials across the 4 n-warps of each m-half, softmax ----
        if (tid < MROWS) {
            const int wmr = tid >> 5;
            float lg = 0.f;
            #pragma unroll
            for (int k = 0; k < 4; k++) lg += lgpart[(wmr*4 + k)*64 + tid];
            lgf[tid] = lg;
        }
        __syncthreads();
        if (tid < RPT) {
            const float* lg = lgf + tid*SAMP;
            float l[SAMP], mx = -1e30f;
            #pragma unroll
            for (int s = 0; s < SAMP; s++) { l[s] = lg[s]; mx = fmaxf(mx, l[s]); }
            float sum = 0.f;
            #pragma unroll
            for (int s = 0; s < SAMP; s++) { l[s] = __expf(l[s] - mx); sum += l[s]; }
            float inv = 1.f / sum;
            #pragma unroll
            for (int s = 0; s < SAMP; s++) alf[tid*SAMP + s] = l[s] * inv;
        }
        __syncthreads();

        // ---- weighted sum of raw nb rows (gmem, L2-resident from convert) ----
        {
            const int col = tid & 127;
            const int grp = tid >> 7;           // 0..1
            const float* nbg = nbp + (size_t)rowBase*(SAMP*DIMD);
            #pragma unroll
            for (int r = grp; r < RPT; r += 2) {
                float acc = 0.f;
                #pragma unroll
                for (int s = 0; s < SAMP; s++)
                    acc = fmaf(alf[r*SAMP + s], __ldg(&nbg[(size_t)(r*SAMP + s)*DIMD + col]), acc);
                outp[(size_t)(rowBase + r)*DIMD + col] = acc;
            }
        }
        __syncthreads();   // epilogue readers done before next tile's convert
    }
}

// ============================================================================
// Final gating via MMA:  z = [h | agg] @ [w3; w4]  (K=256, bf16 3-term hi/lo)
//   agg = s0*a0 + s1*b0;  out = (1-sig(z))*h + sig(z)*agg
// 3200 rows = 50 tiles x 64 rows. B (w3,w4) resident in smem.
// ============================================================================
#define FB3_HI 0
#define FB4_HI 32768
#define FB3_LO 65536
#define FB4_LO 98304
#define FA0_HI 131072
#define FA1_HI 147456
#define FA0_LO 163840
#define FA1_LO 180224
#define FSMEM  196608

__global__ void __launch_bounds__(256, 1)
final_mma(const float* __restrict__ hidden,
          const float* __restrict__ a0,
          const float* __restrict__ b0,
          const float* __restrict__ w3,
          const float* __restrict__ w4,
          const float* __restrict__ sw,
          float* __restrict__ out)
{
    extern __shared__ __align__(128) char sm[];
    const uint32_t smb = smem_u32(sm);
    const int tid  = threadIdx.x;
    const int lane = tid & 31;
    const int warp = tid >> 5;
    const int wm   = warp >> 2;         // m-half (32 rows)
    const int wn   = warp & 3;          // n-slice (32 cols)
    const int tileBase = blockIdx.x * 64;

    const float s0 = __ldg(&sw[0]);
    const float s1 = __ldg(&sw[1]);

    // ---- stage B = w3 / w4 hi/lo into persistent planes ----
    for (int i = tid; i < DIMD*DIMD; i += 256) {
        int d = i >> 7, n = i & 127;
        uint32_t off = (uint32_t)n*256u + ((uint32_t)(((d>>3) ^ (n & 7))) << 4) + ((uint32_t)(d & 7) << 1);
        float w = w3[i];
        __nv_bfloat16 hb = __float2bfloat16(w);
        __nv_bfloat16 lb = __float2bfloat16(w - __bfloat162float(hb));
        *(__nv_bfloat16*)(sm + FB3_HI + off) = hb;
        *(__nv_bfloat16*)(sm + FB3_LO + off) = lb;
        w = w4[i];
        hb = __float2bfloat16(w);
        lb = __float2bfloat16(w - __bfloat162float(hb));
        *(__nv_bfloat16*)(sm + FB4_HI + off) = hb;
        *(__nv_bfloat16*)(sm + FB4_LO + off) = lb;
    }

    // ---- convert A: plane0 = h, plane1 = agg; 64 rows x 32 granules each ----
    {
        const int half = tid & 1;
        const int r    = (tid >> 1) & 63;
        const int gBase = (tid >= 128) ? 16 : 0;
        const uint32_t hiOff = half ? FA1_HI : FA0_HI;
        const uint32_t loOff = half ? FA1_LO : FA0_LO;
        const float4* src  = (const float4*)(hidden + (size_t)(tileBase + r)*DIMD);
        const float4* srcA = (const float4*)(a0 + (size_t)(tileBase + r)*DIMD);
        const float4* srcB = (const float4*)(b0 + (size_t)(tileBase + r)*DIMD);
        #pragma unroll 4
        for (int g = gBase; g < gBase + 16; g++) {
            float4 v;
            if (half == 0) {
                v = src[g];
            } else {
                float4 va = srcA[g], vb = srcB[g];
                v.x = fmaf(va.x, s0, vb.x*s1); v.y = fmaf(va.y, s0, vb.y*s1);
                v.z = fmaf(va.z, s0, vb.z*s1); v.w = fmaf(va.w, s0, vb.w*s1);
            }
            __nv_bfloat162 h01 = __floats2bfloat162_rn(v.x, v.y);
            __nv_bfloat162 h23 = __floats2bfloat162_rn(v.z, v.w);
            float2 f01 = __bfloat1622float2(h01);
            float2 f23 = __bfloat1622float2(h23);
            __nv_bfloat162 l01 = __floats2bfloat162_rn(v.x - f01.x, v.y - f01.y);
            __nv_bfloat162 l23 = __floats2bfloat162_rn(v.z - f23.x, v.w - f23.y);
            uint32_t off = (uint32_t)r*256u + ((uint32_t)(((g>>1) ^ (r & 7))) << 4) + ((uint32_t)(g & 1) << 3);
            *(__nv_bfloat162*)(sm + hiOff + off)     = h01;
            *(__nv_bfloat162*)(sm + hiOff + off + 4) = h23;
            *(__nv_bfloat162*)(sm + loOff + off)     = l01;
            *(__nv_bfloat162*)(sm + loOff + off + 4) = l23;
        }
    }
    __syncthreads();

    // ---- MMA over K=256; B from smem ----
    const uint32_t aLaneRow = (uint32_t)(lane & 15) * 256u;
    const uint32_t aCk      = (uint32_t)(lane >> 4);
    const uint32_t aSwz     = (uint32_t)(lane & 7);
    const uint32_t l7       = (uint32_t)(lane & 7);
    const uint32_t ck4      = ((uint32_t)lane >> 3) & 3;

    float d[2][4][4];
    #pragma unroll
    for (int s = 0; s < 2; s++)
        #pragma unroll
        for (int j = 0; j < 4; j++)
            #pragma unroll
            for (int i = 0; i < 4; i++) d[s][j][i] = 0.f;

    #pragma unroll
    for (int p = 0; p < 8; p++) {
        const uint32_t bHi = (p < 4) ? FB3_HI : FB4_HI;
        const uint32_t bLo = (p < 4) ? FB3_LO : FB4_LO;
        const uint32_t aHi = (p < 4) ? FA0_HI : FA1_HI;
        const uint32_t aLo = (p < 4) ? FA0_LO : FA1_LO;
        const int pp = p & 3;
        uint32_t Bh[4][4], Bl[4][4];
        #pragma unroll
        for (int j = 0; j < 4; j++) {
            const uint32_t row8 = (uint32_t)(wn*32 + j*8) + l7;
            const uint32_t term = row8*256u + ((((uint32_t)(4*pp) + ck4) ^ (row8 & 7)) << 4);
            ldsm4(Bh[j][0], Bh[j][1], Bh[j][2], Bh[j][3], smb + bHi + term);
            ldsm4(Bl[j][0], Bl[j][1], Bl[j][2], Bl[j][3], smb + bLo + term);
        }
        #pragma unroll
        for (int qq = 0; qq < 2; qq++) {
            const int q = 2*pp + qq;
            const uint32_t koff = ((((uint32_t)(2*q) + aCk) ^ aSwz) << 4);
            #pragma unroll
            for (int s = 0; s < 2; s++) {
                const uint32_t aoff = (uint32_t)(wm*2 + s)*4096u + aLaneRow + koff;
                uint32_t ah[4], al[4];
                ldsm4(ah[0], ah[1], ah[2], ah[3], smb + aHi + aoff);
                ldsm4(al[0], al[1], al[2], al[3], smb + aLo + aoff);
                #pragma unroll
                for (int j = 0; j < 4; j++) mma_bf16(d[s][j], ah, Bh[j][qq*2], Bh[j][qq*2+1]);
                #pragma unroll
                for (int j = 0; j < 4; j++) mma_bf16(d[s][j], al, Bh[j][qq*2], Bh[j][qq*2+1]);
                #pragma unroll
                for (int j = 0; j < 4; j++) mma_bf16(d[s][j], ah, Bl[j][qq*2], Bl[j][qq*2+1]);
            }
        }
    }

    // ---- epilogue: sig = sigmoid(z); out = (1-sig)*h + sig*agg ----
    {
        const int lq = lane & 3;
        const int rq = lane >> 2;
        #pragma unroll
        for (int s = 0; s < 2; s++) {
            #pragma unroll
            for (int j = 0; j < 4; j++) {
                const int c0 = wn*32 + j*8 + lq*2;
                const int g  = c0 >> 2;
                const uint32_t pairAdd = ((uint32_t)((c0 >> 1) & 1)) << 2;
                #pragma unroll
                for (int half = 0; half < 2; half++) {
                    const int row = wm*32 + s*16 + rq + half*8;   // <= 63
                    const uint32_t off = (uint32_t)row*256u
                        + ((uint32_t)(((g>>1) ^ (row & 7))) << 4)
                        + ((uint32_t)(g & 1) << 3) + pairAdd;
                    float2 hhi = __bfloat1622float2(*(__nv_bfloat162*)(sm + FA0_HI + off));
                    float2 hlo = __bfloat1622float2(*(__nv_bfloat162*)(sm + FA0_LO + off));
                    float2 ghi = __bfloat1622float2(*(__nv_bfloat162*)(sm + FA1_HI + off));
                    float2 glo = __bfloat1622float2(*(__nv_bfloat162*)(sm + FA1_LO + off));
                    const float h0 = hhi.x + hlo.x, h1 = hhi.y + hlo.y;
                    const float a0v = ghi.x + glo.x, a1v = ghi.y + glo.y;
                    const float z0 = d[s][j][half*2 + 0];
                    const float z1 = d[s][j][half*2 + 1];
                    const float sg0 = 1.f / (1.f + __expf(-z0));
                    const float sg1 = 1.f / (1.f + __expf(-z1));
                    float2 o;
                    o.x = (1.f - sg0)*h0 + sg0*a0v;
                    o.y = (1.f - sg1)*h1 + sg1*a1v;
                    *(float2*)(out + (size_t)(tileBase + row)*DIMD + c0) = o;
                }
            }
        }
    }
}

extern "C" void kernel_launch(void* const* d_in, const int* in_sizes, int n_in,
                              void* d_out, int out_size)
{
    const float* hidden = (const float*)d_in[0];
    const float* nh1    = (const float*)d_in[1];
    const float* nh2    = (const float*)d_in[2];
    const float* nw0    = (const float*)d_in[3];
    const float* nw1    = (const float*)d_in[4];
    const float* w1     = (const float*)d_in[5];
    const float* w2     = (const float*)d_in[6];
    const float* w3     = (const float*)d_in[7];
    const float* w4     = (const float*)d_in[8];
    const float* sv     = (const float*)d_in[9];
    float* out = (float*)d_out;

    float *a0, *a1, *b0;
    cudaGetSymbolAddress((void**)&a0, g_a0);
    cudaGetSymbolAddress((void**)&a1, g_a1);
    cudaGetSymbolAddress((void**)&b0, g_b0);

    cudaFuncSetAttribute(agg_kernel, cudaFuncAttributeMaxDynamicSharedMemorySize, SMEM_TOTAL);
    cudaFuncSetAttribute(final_mma, cudaFuncAttributeMaxDynamicSharedMemorySize, FSMEM);

    const int GRID = 296;   // 2 CTAs/SM (104.7 KB smem, <=128 regs), persistent tiles
    const int T_A = 640;    // 3200/5
    const int T_B = 7680;   // 38400/5
    const int T_C = 640;

    // Stages A+B merged (independent): tiles [0,640) -> a0, [640,8320) -> a1
    agg_kernel<<<GRID, NT, SMEM_TOTAL>>>(hidden, nh1, nw0, a0, T_A,
                                         nh1, nh2, nw1, a1, T_A + T_B, w1, w2);
    // Stage C: agg(a0, a1, nw0) -> b0   [640 tiles]
    agg_kernel<<<GRID, NT, SMEM_TOTAL>>>(a0, a1, nw0, b0, T_C,
                                         a0, a1, nw0, b0, T_C, w1, w2);
    // Final gating via MMA: 50 tiles of 64 rows
    final_mma<<<50, 256, FSMEM>>>(hidden, a0, b0, w3, w4, sv, out);
}